// round 3
// baseline (speedup 1.0000x reference)
#include <cuda_runtime.h>
#include <cstdint>
#include <cstddef>

// Problem dims
#define UCNT 32
#define BBAT 256
#define DDIM 768
#define KDIM 3072   // P*D = 4*768

// GEMM tiling
#define BM 256
#define BN 64
#define BK 16
#define BKP 20      // padded A tile row (conflict-free frag reads)
#define BNP 72      // padded B tile row (conflict-free frag reads)
#define NKT (KDIM / BK)   // 192 k-tiles

__device__ __forceinline__ uint32_t f2tf32(float f) {
    uint32_t r;
    asm("cvt.rna.tf32.f32 %0, %1;" : "=r"(r) : "f"(f));
    return r;
}

// C[u, 0:256, n0:n0+64] = A[256,3072] @ W[u][3072,768] + bias[u]
__global__ __launch_bounds__(256, 2)
void coldprompt_gemm_tf32(const float* __restrict__ A,     // [256, 3072]
                          const float* __restrict__ W,     // [32, 3072, 768]
                          const float* __restrict__ bias,  // [32, 768]
                          float* __restrict__ out)         // [32*256, 768]
{
    extern __shared__ float smem[];
    float* As = smem;                      // [2][BM][BKP]
    float* Bs = smem + 2 * BM * BKP;       // [2][BK][BNP]

    const int u    = blockIdx.y;
    const int n0   = blockIdx.x * BN;
    const int tid  = threadIdx.x;
    const int warp = tid >> 5;
    const int lane = tid & 31;
    const int g    = lane >> 2;   // 0..7
    const int tg   = lane & 3;    // 0..3

    const float* Wu = W + (size_t)u * KDIM * DDIM;

    // staging: A tile 256x16 -> one row (4x16B) per thread
    const int aRow = tid;
    // B tile 16x64 -> 256 chunks of 16B, 1 per thread
    const int bRow = tid >> 4;          // 0..15
    const int bCol = (tid & 15) << 2;   // 0,4,...,60

    const uint32_t asBase = (uint32_t)__cvta_generic_to_shared(As);
    const uint32_t bsBase = (uint32_t)__cvta_generic_to_shared(Bs);

    auto load_tiles = [&](int kt, int buf) {
        const int kBase = kt * BK;
        const float* ag = A + (size_t)aRow * KDIM + kBase;
        uint32_t as = asBase + (uint32_t)((buf * BM * BKP + aRow * BKP) * 4);
        #pragma unroll
        for (int c = 0; c < 4; c++) {
            asm volatile("cp.async.cg.shared.global [%0], [%1], 16;\n"
                         :: "r"(as + c * 16), "l"(ag + c * 4));
        }
        const float* bg = Wu + (size_t)(kBase + bRow) * DDIM + n0 + bCol;
        uint32_t bs = bsBase + (uint32_t)((buf * BK * BNP + bRow * BNP + bCol) * 4);
        asm volatile("cp.async.cg.shared.global [%0], [%1], 16;\n"
                     :: "r"(bs), "l"(bg));
        asm volatile("cp.async.commit_group;\n");
    };

    float acc[2][8][4];
    #pragma unroll
    for (int i = 0; i < 2; i++)
        #pragma unroll
        for (int j = 0; j < 8; j++)
            #pragma unroll
            for (int c = 0; c < 4; c++) acc[i][j][c] = 0.0f;

    load_tiles(0, 0);

    for (int kt = 0; kt < NKT; kt++) {
        const int buf = kt & 1;
        if (kt + 1 < NKT) {
            load_tiles(kt + 1, buf ^ 1);
            asm volatile("cp.async.wait_group 1;\n");
        } else {
            asm volatile("cp.async.wait_group 0;\n");
        }
        __syncthreads();

        const float* Asb = As + buf * BM * BKP;
        const float* Bsb = Bs + buf * BK * BNP;

        #pragma unroll
        for (int ks = 0; ks < 2; ks++) {
            const int k0 = ks * 8;
            uint32_t aF[2][4];
            #pragma unroll
            for (int mt = 0; mt < 2; mt++) {
                const int mBase = warp * 32 + mt * 16;
                aF[mt][0] = f2tf32(Asb[(mBase + g)     * BKP + k0 + tg]);
                aF[mt][1] = f2tf32(Asb[(mBase + g + 8) * BKP + k0 + tg]);
                aF[mt][2] = f2tf32(Asb[(mBase + g)     * BKP + k0 + tg + 4]);
                aF[mt][3] = f2tf32(Asb[(mBase + g + 8) * BKP + k0 + tg + 4]);
            }
            uint32_t bF[8][2];
            #pragma unroll
            for (int nt = 0; nt < 8; nt++) {
                const int nBase = nt * 8;
                bF[nt][0] = f2tf32(Bsb[(k0 + tg)     * BNP + nBase + g]);
                bF[nt][1] = f2tf32(Bsb[(k0 + tg + 4) * BNP + nBase + g]);
            }
            #pragma unroll
            for (int mt = 0; mt < 2; mt++)
                #pragma unroll
                for (int nt = 0; nt < 8; nt++) {
                    asm volatile(
                        "mma.sync.aligned.m16n8k8.row.col.f32.tf32.tf32.f32 "
                        "{%0,%1,%2,%3}, {%4,%5,%6,%7}, {%8,%9}, {%0,%1,%2,%3};\n"
                        : "+f"(acc[mt][nt][0]), "+f"(acc[mt][nt][1]),
                          "+f"(acc[mt][nt][2]), "+f"(acc[mt][nt][3])
                        : "r"(aF[mt][0]), "r"(aF[mt][1]), "r"(aF[mt][2]), "r"(aF[mt][3]),
                          "r"(bF[nt][0]), "r"(bF[nt][1]));
                }
        }
        __syncthreads();
    }

    // Epilogue: add bias, write fp32
    const float* bu  = bias + u * DDIM + n0;
    float* outU = out + (size_t)u * BBAT * DDIM + n0;
    #pragma unroll
    for (int mt = 0; mt < 2; mt++) {
        const int mBase = warp * 32 + mt * 16;
        #pragma unroll
        for (int nt = 0; nt < 8; nt++) {
            const int col0 = nt * 8 + 2 * tg;
            const float bv0 = bu[col0];
            const float bv1 = bu[col0 + 1];
            outU[(size_t)(mBase + g)     * DDIM + col0]     = acc[mt][nt][0] + bv0;
            outU[(size_t)(mBase + g)     * DDIM + col0 + 1] = acc[mt][nt][1] + bv1;
            outU[(size_t)(mBase + g + 8) * DDIM + col0]     = acc[mt][nt][2] + bv0;
            outU[(size_t)(mBase + g + 8) * DDIM + col0 + 1] = acc[mt][nt][3] + bv1;
        }
    }
}

// mean_emb[b, d] = mean over P of weight[b, p, d]
__global__ void coldprompt_mean(const float* __restrict__ w, float* __restrict__ out)
{
    const int i = blockIdx.x * blockDim.x + threadIdx.x;
    if (i < BBAT * DDIM) {
        const int b = i / DDIM;
        const int d = i % DDIM;
        const float* p = w + (size_t)b * 4 * DDIM + d;
        out[i] = 0.25f * (p[0] + p[DDIM] + p[2 * DDIM] + p[3 * DDIM]);
    }
}

extern "C" void kernel_launch(void* const* d_in, const int* in_sizes, int n_in,
                              void* d_out, int out_size)
{
    const float* weight = nullptr;   // [256, 4, 768]
    const float* W      = nullptr;   // [32, 3072, 768]
    const float* bias   = nullptr;   // [32, 768]
    for (int i = 0; i < n_in; i++) {
        if      (in_sizes[i] == BBAT * 4 * DDIM)        weight = (const float*)d_in[i];
        else if (in_sizes[i] == UCNT * KDIM * DDIM)     W      = (const float*)d_in[i];
        else if (in_sizes[i] == UCNT * DDIM)            bias   = (const float*)d_in[i];
    }
    float* out = (float*)d_out;

    const int smemBytes = (2 * BM * BKP + 2 * BK * BNP) * 4;  // 50176 B
    cudaFuncSetAttribute(coldprompt_gemm_tf32,
                         cudaFuncAttributeMaxDynamicSharedMemorySize, smemBytes);

    dim3 grid(DDIM / BN, UCNT);   // (12, 32)
    coldprompt_gemm_tf32<<<grid, 256, smemBytes>>>(weight, W, bias, out);

    const int meanElems = BBAT * DDIM;
    coldprompt_mean<<<(meanElems + 255) / 256, 256>>>(
        weight, out + (size_t)UCNT * BBAT * DDIM);

    (void)out_size;
}